// round 1
// baseline (speedup 1.0000x reference)
#include <cuda_runtime.h>
#include <math.h>

#define C_CH 64
#define NPTS 500000
#define NC (NPTS * C_CH)          // 32,000,000
#define NC4 (NC / 4)              // 8,000,000

// ---------------- device-global precomputed parameters ----------------
// Fast path: per-channel affine composition, stored as float4 groups of 4
// consecutive channels (threads load channels [4g..4g+3] with one LDG.128).
__device__ float4 g_A4[16];
__device__ float4 g_Bl4[16];
__device__ float4 g_Bu4[16];
__device__ int    g_fast;

// General path (any f != 0): softplus(m), biases, tanh(f) per channel/layer.
__device__ float g_sp0[C_CH * 3], g_b0v[C_CH * 3], g_tf0[C_CH * 3];
__device__ float g_sp1[C_CH * 9], g_b1v[C_CH * 3], g_tf1[C_CH * 3];
__device__ float g_sp2[C_CH * 9], g_b2v[C_CH * 3], g_tf2[C_CH * 3];
__device__ float g_sp3[C_CH * 3], g_b3v[C_CH],     g_tf3[C_CH];

// ---------------- prelude: precompute per-channel params ----------------
__global__ void eb_prelude(
    const float* __restrict__ m0, const float* __restrict__ b0, const float* __restrict__ f0,
    const float* __restrict__ m1, const float* __restrict__ b1, const float* __restrict__ f1,
    const float* __restrict__ m2, const float* __restrict__ b2, const float* __restrict__ f2,
    const float* __restrict__ m3, const float* __restrict__ b3, const float* __restrict__ f3)
{
    int c = threadIdx.x;          // 64 threads, one channel each
    __shared__ int s_fast;
    if (c == 0) s_fast = 1;
    __syncthreads();

    // softplus in double for accuracy
    double sp0[3], sp1[9], sp2[9], sp3[3];
    for (int j = 0; j < 3; j++) sp0[j] = log1p(exp((double)m0[c * 3 + j]));
    for (int j = 0; j < 9; j++) sp1[j] = log1p(exp((double)m1[c * 9 + j]));
    for (int j = 0; j < 9; j++) sp2[j] = log1p(exp((double)m2[c * 9 + j]));
    for (int j = 0; j < 3; j++) sp3[j] = log1p(exp((double)m3[c * 3 + j]));

    bool fz = true;
    for (int j = 0; j < 3; j++) {
        if (f0[c * 3 + j] != 0.f) fz = false;
        if (f1[c * 3 + j] != 0.f) fz = false;
        if (f2[c * 3 + j] != 0.f) fz = false;
    }
    if (f3[c] != 0.f) fz = false;
    if (!fz) atomicAnd(&s_fast, 0);

    // store general-path params
    for (int j = 0; j < 3; j++) {
        g_sp0[c * 3 + j] = (float)sp0[j];
        g_b0v[c * 3 + j] = b0[c * 3 + j];
        g_tf0[c * 3 + j] = tanhf(f0[c * 3 + j]);
        g_b1v[c * 3 + j] = b1[c * 3 + j];
        g_tf1[c * 3 + j] = tanhf(f1[c * 3 + j]);
        g_b2v[c * 3 + j] = b2[c * 3 + j];
        g_tf2[c * 3 + j] = tanhf(f2[c * 3 + j]);
        g_sp3[c * 3 + j] = (float)sp3[j];
    }
    for (int j = 0; j < 9; j++) { g_sp1[c * 9 + j] = (float)sp1[j]; g_sp2[c * 9 + j] = (float)sp2[j]; }
    g_b3v[c] = b3[c];
    g_tf3[c] = tanhf(f3[c]);

    // compose affine chain (valid when all gates are zero) in double
    double a[3], bb[3];
    for (int j = 0; j < 3; j++) { a[j] = sp0[j]; bb[j] = (double)b0[c * 3 + j]; }
    double a1[3], bv1[3];
    for (int i = 0; i < 3; i++) {
        double av = 0.0, bv = (double)b1[c * 3 + i];
        for (int j = 0; j < 3; j++) { av += sp1[i * 3 + j] * a[j]; bv += sp1[i * 3 + j] * bb[j]; }
        a1[i] = av; bv1[i] = bv;
    }
    double a2[3], bv2[3];
    for (int i = 0; i < 3; i++) {
        double av = 0.0, bv = (double)b2[c * 3 + i];
        for (int j = 0; j < 3; j++) { av += sp2[i * 3 + j] * a1[j]; bv += sp2[i * 3 + j] * bv1[j]; }
        a2[i] = av; bv2[i] = bv;
    }
    double A = 0.0, B = (double)b3[c];
    for (int j = 0; j < 3; j++) { A += sp3[j] * a2[j]; B += sp3[j] * bv2[j]; }

    float* Af  = (float*)g_A4;
    float* Blf = (float*)g_Bl4;
    float* Buf = (float*)g_Bu4;
    Af[c]  = (float)A;
    Blf[c] = (float)(B - 0.5 * A);
    Buf[c] = (float)(B + 0.5 * A);

    __syncthreads();
    if (c == 0) g_fast = s_fast;
}

// ---------------- likelihood helpers ----------------
__device__ __forceinline__ float sig_diff_clamp(float u, float l)
{
    // sign = -sign(l+u); likelihood = |sigmoid(s*u) - sigmoid(s*l)|, clamped.
    float t = u + l;
    float s = (t > 0.f) ? -1.f : ((t < 0.f) ? 1.f : 0.f);
    float ea = __expf(s * u);
    float eb = __expf(s * l);
    // sig(a)-sig(b) = (e^a - e^b) / ((1+e^a)(1+e^b))
    float d = __fdividef(ea - eb, (1.f + ea) * (1.f + eb));
    return fmaxf(fabsf(d), 1e-9f);
}

__device__ __forceinline__ float lik_fast(float x, float A, float Bl, float Bu)
{
    float u = fmaf(A, x, Bu);
    float l = fmaf(A, x, Bl);
    return sig_diff_clamp(u, l);
}

__device__ float chain_general(float x, int c)
{
    float h[3], h2[3];
    #pragma unroll
    for (int j = 0; j < 3; j++) {
        float v = fmaf(g_sp0[c * 3 + j], x, g_b0v[c * 3 + j]);
        h[j] = v + g_tf0[c * 3 + j] * tanhf(v);
    }
    #pragma unroll
    for (int i = 0; i < 3; i++) {
        float v = g_b1v[c * 3 + i];
        #pragma unroll
        for (int j = 0; j < 3; j++) v = fmaf(g_sp1[c * 9 + i * 3 + j], h[j], v);
        h2[i] = v + g_tf1[c * 3 + i] * tanhf(v);
    }
    #pragma unroll
    for (int i = 0; i < 3; i++) {
        float v = g_b2v[c * 3 + i];
        #pragma unroll
        for (int j = 0; j < 3; j++) v = fmaf(g_sp2[c * 9 + i * 3 + j], h2[j], v);
        h[i] = v + g_tf2[c * 3 + i] * tanhf(v);
    }
    float v = g_b3v[c];
    #pragma unroll
    for (int j = 0; j < 3; j++) v = fmaf(g_sp3[c * 3 + j], h[j], v);
    return v + g_tf3[c] * tanhf(v);
}

__device__ __forceinline__ float lik_general(float x, int c)
{
    float u = chain_general(x + 0.5f, c);
    float l = chain_general(x - 0.5f, c);
    return sig_diff_clamp(u, l);
}

// ---------------- main kernel ----------------
__global__ void __launch_bounds__(256)
eb_main(const float4* __restrict__ in, const float4* __restrict__ noise,
        float4* __restrict__ out_o, float4* __restrict__ out_l, int write_outputs)
{
    int i = blockIdx.x * blockDim.x + threadIdx.x;
    if (i >= NC4) return;

    int cg = i & 15;              // float4 channel-group 0..15 (channels 4*cg..4*cg+3)

    float4 x4 = in[i];
    float4 n4 = noise[i];
    x4.x += n4.x; x4.y += n4.y; x4.z += n4.z; x4.w += n4.w;
    if (write_outputs) out_o[i] = x4;

    float4 lk;
    if (g_fast) {
        float4 A  = g_A4[cg];
        float4 Bl = g_Bl4[cg];
        float4 Bu = g_Bu4[cg];
        lk.x = lik_fast(x4.x, A.x, Bl.x, Bu.x);
        lk.y = lik_fast(x4.y, A.y, Bl.y, Bu.y);
        lk.z = lik_fast(x4.z, A.z, Bl.z, Bu.z);
        lk.w = lik_fast(x4.w, A.w, Bl.w, Bu.w);
    } else {
        int c0 = cg * 4;
        lk.x = lik_general(x4.x, c0 + 0);
        lk.y = lik_general(x4.y, c0 + 1);
        lk.z = lik_general(x4.z, c0 + 2);
        lk.w = lik_general(x4.w, c0 + 3);
    }
    out_l[i] = lk;
}

// ---------------- launch ----------------
extern "C" void kernel_launch(void* const* d_in, const int* in_sizes, int n_in,
                              void* d_out, int out_size)
{
    const float* inputs = (const float*)d_in[0];
    const float* noise  = (const float*)d_in[1];
    const float* m0 = (const float*)d_in[2];
    const float* b0 = (const float*)d_in[3];
    const float* f0 = (const float*)d_in[4];
    const float* m1 = (const float*)d_in[5];
    const float* b1 = (const float*)d_in[6];
    const float* f1 = (const float*)d_in[7];
    const float* m2 = (const float*)d_in[8];
    const float* b2 = (const float*)d_in[9];
    const float* f2 = (const float*)d_in[10];
    const float* m3 = (const float*)d_in[11];
    const float* b3 = (const float*)d_in[12];
    const float* f3 = (const float*)d_in[13];

    float* out = (float*)d_out;
    float* out_outputs;
    float* out_lik;
    int write_outputs;
    if (out_size >= 2 * NC) {
        out_outputs = out;          // (N, C) outputs first
        out_lik     = out + NC;     // then (N, C) likelihood
        write_outputs = 1;
    } else {
        out_outputs = out;          // unused
        out_lik     = out;          // likelihood only
        write_outputs = 0;
    }

    eb_prelude<<<1, 64>>>(m0, b0, f0, m1, b1, f1, m2, b2, f2, m3, b3, f3);

    int blocks = (NC4 + 255) / 256;
    eb_main<<<blocks, 256>>>((const float4*)inputs, (const float4*)noise,
                             (float4*)out_outputs, (float4*)out_lik, write_outputs);
}

// round 3
// speedup vs baseline: 1.5355x; 1.5355x over previous
#include <cuda_runtime.h>
#include <math.h>

#define C_CH 64
#define NPTS 500000
#define NC (NPTS * C_CH)          // 32,000,000
#define NC4 (NC / 4)              // 8,000,000

// ---------------- device-global precomputed parameters ----------------
__device__ float4 g_A4[16];
__device__ float4 g_Bu4[16];
__device__ int    g_fast;

// General path (any f != 0): softplus(m), biases, tanh(f) per channel/layer.
__device__ float g_sp0[C_CH * 3], g_b0v[C_CH * 3], g_tf0[C_CH * 3];
__device__ float g_sp1[C_CH * 9], g_b1v[C_CH * 3], g_tf1[C_CH * 3];
__device__ float g_sp2[C_CH * 9], g_b2v[C_CH * 3], g_tf2[C_CH * 3];
__device__ float g_sp3[C_CH * 3], g_b3v[C_CH],     g_tf3[C_CH];

// ---------------- prelude: precompute per-channel params (all fp32) --------
__global__ void __launch_bounds__(64)
eb_prelude(
    const float* __restrict__ m0, const float* __restrict__ b0, const float* __restrict__ f0,
    const float* __restrict__ m1, const float* __restrict__ b1, const float* __restrict__ f1,
    const float* __restrict__ m2, const float* __restrict__ b2, const float* __restrict__ f2,
    const float* __restrict__ m3, const float* __restrict__ b3, const float* __restrict__ f3)
{
    int c = threadIdx.x;          // 64 threads, one channel each

    float sp0[3], sp1[9], sp2[9], sp3[3];
    #pragma unroll
    for (int j = 0; j < 3; j++) sp0[j] = log1pf(expf(m0[c * 3 + j]));
    #pragma unroll
    for (int j = 0; j < 9; j++) sp1[j] = log1pf(expf(m1[c * 9 + j]));
    #pragma unroll
    for (int j = 0; j < 9; j++) sp2[j] = log1pf(expf(m2[c * 9 + j]));
    #pragma unroll
    for (int j = 0; j < 3; j++) sp3[j] = log1pf(expf(m3[c * 3 + j]));

    bool fz = true;
    #pragma unroll
    for (int j = 0; j < 3; j++) {
        if (f0[c * 3 + j] != 0.f) fz = false;
        if (f1[c * 3 + j] != 0.f) fz = false;
        if (f2[c * 3 + j] != 0.f) fz = false;
    }
    if (f3[c] != 0.f) fz = false;

    // store general-path params
    #pragma unroll
    for (int j = 0; j < 3; j++) {
        g_sp0[c * 3 + j] = sp0[j];
        g_b0v[c * 3 + j] = b0[c * 3 + j];
        g_tf0[c * 3 + j] = tanhf(f0[c * 3 + j]);
        g_b1v[c * 3 + j] = b1[c * 3 + j];
        g_tf1[c * 3 + j] = tanhf(f1[c * 3 + j]);
        g_b2v[c * 3 + j] = b2[c * 3 + j];
        g_tf2[c * 3 + j] = tanhf(f2[c * 3 + j]);
        g_sp3[c * 3 + j] = sp3[j];
    }
    #pragma unroll
    for (int j = 0; j < 9; j++) { g_sp1[c * 9 + j] = sp1[j]; g_sp2[c * 9 + j] = sp2[j]; }
    g_b3v[c] = b3[c];
    g_tf3[c] = tanhf(f3[c]);

    // compose affine chain (valid when all gates are zero), fp32
    float a0[3], bb[3];
    #pragma unroll
    for (int j = 0; j < 3; j++) { a0[j] = sp0[j]; bb[j] = b0[c * 3 + j]; }
    float a1[3], bv1[3];
    #pragma unroll
    for (int i = 0; i < 3; i++) {
        float av = 0.f, bv = b1[c * 3 + i];
        #pragma unroll
        for (int j = 0; j < 3; j++) { av = fmaf(sp1[i * 3 + j], a0[j], av); bv = fmaf(sp1[i * 3 + j], bb[j], bv); }
        a1[i] = av; bv1[i] = bv;
    }
    float a2[3], bv2[3];
    #pragma unroll
    for (int i = 0; i < 3; i++) {
        float av = 0.f, bv = b2[c * 3 + i];
        #pragma unroll
        for (int j = 0; j < 3; j++) { av = fmaf(sp2[i * 3 + j], a1[j], av); bv = fmaf(sp2[i * 3 + j], bv1[j], bv); }
        a2[i] = av; bv2[i] = bv;
    }
    float A = 0.f, B = b3[c];
    #pragma unroll
    for (int j = 0; j < 3; j++) { A = fmaf(sp3[j], a2[j], A); B = fmaf(sp3[j], bv2[j], B); }

    ((float*)g_A4)[c]  = A;
    ((float*)g_Bu4)[c] = B + 0.5f * A;

    // all-channels AND across the block: g_fast = 1 iff every gate is zero
    int all_fz = __syncthreads_and(fz ? 1 : 0);
    if (c == 0) g_fast = all_fz;
}

// ---------------- likelihood helpers ----------------
__device__ __forceinline__ float sig_diff_clamp(float u, float l)
{
    // sign = -sign(l+u); likelihood = |sigmoid(s*u) - sigmoid(s*l)|, clamped.
    float t = u + l;
    float s = (t > 0.f) ? -1.f : ((t < 0.f) ? 1.f : 0.f);
    float ea = __expf(s * u);
    float eb = __expf(s * l);
    // sig(a)-sig(b) = (e^a - e^b) / ((1+e^a)(1+e^b))
    float d = __fdividef(ea - eb, (1.f + ea) * (1.f + eb));
    return fmaxf(fabsf(d), 1e-9f);
}

// ---------------- fast-path main kernel (affine chain) ----------------
__global__ void __launch_bounds__(256, 6)
eb_main_fast(const float4* __restrict__ in, const float4* __restrict__ noise,
             float4* __restrict__ out_o, float4* __restrict__ out_l, int write_outputs)
{
    int i = blockIdx.x * blockDim.x + threadIdx.x;
    if (i >= NC4) return;

    int cg = i & 15;              // float4 channel-group 0..15

    float4 x4 = in[i];
    float4 n4 = noise[i];
    x4.x += n4.x; x4.y += n4.y; x4.z += n4.z; x4.w += n4.w;
    if (write_outputs) out_o[i] = x4;

    float4 A  = g_A4[cg];
    float4 Bu = g_Bu4[cg];

    float ux = fmaf(A.x, x4.x, Bu.x);
    float uy = fmaf(A.y, x4.y, Bu.y);
    float uz = fmaf(A.z, x4.z, Bu.z);
    float uw = fmaf(A.w, x4.w, Bu.w);

    float4 lk;
    lk.x = sig_diff_clamp(ux, ux - A.x);
    lk.y = sig_diff_clamp(uy, uy - A.y);
    lk.z = sig_diff_clamp(uz, uz - A.z);
    lk.w = sig_diff_clamp(uw, uw - A.w);

    out_l[i] = lk;
}

// ---------------- general-path kernel (only runs if any f != 0) ----------
__device__ float chain_general(float x, int c)
{
    float h[3], h2[3];
    #pragma unroll
    for (int j = 0; j < 3; j++) {
        float v = fmaf(g_sp0[c * 3 + j], x, g_b0v[c * 3 + j]);
        h[j] = v + g_tf0[c * 3 + j] * tanhf(v);
    }
    #pragma unroll
    for (int i = 0; i < 3; i++) {
        float v = g_b1v[c * 3 + i];
        #pragma unroll
        for (int j = 0; j < 3; j++) v = fmaf(g_sp1[c * 9 + i * 3 + j], h[j], v);
        h2[i] = v + g_tf1[c * 3 + i] * tanhf(v);
    }
    #pragma unroll
    for (int i = 0; i < 3; i++) {
        float v = g_b2v[c * 3 + i];
        #pragma unroll
        for (int j = 0; j < 3; j++) v = fmaf(g_sp2[c * 9 + i * 3 + j], h2[j], v);
        h[i] = v + g_tf2[c * 3 + i] * tanhf(v);
    }
    float v = g_b3v[c];
    #pragma unroll
    for (int j = 0; j < 3; j++) v = fmaf(g_sp3[c * 3 + j], h[j], v);
    return v + g_tf3[c] * tanhf(v);
}

__global__ void __launch_bounds__(256)
eb_main_general(const float4* __restrict__ in, const float4* __restrict__ noise,
                float4* __restrict__ out_l)
{
    if (g_fast) return;           // uniform branch: whole grid no-ops on fast data

    int i = blockIdx.x * blockDim.x + threadIdx.x;
    if (i >= NC4) return;
    int cg = i & 15;
    int c0 = cg * 4;

    float4 x4 = in[i];
    float4 n4 = noise[i];
    x4.x += n4.x; x4.y += n4.y; x4.z += n4.z; x4.w += n4.w;

    float4 lk;
    lk.x = sig_diff_clamp(chain_general(x4.x + 0.5f, c0 + 0), chain_general(x4.x - 0.5f, c0 + 0));
    lk.y = sig_diff_clamp(chain_general(x4.y + 0.5f, c0 + 1), chain_general(x4.y - 0.5f, c0 + 1));
    lk.z = sig_diff_clamp(chain_general(x4.z + 0.5f, c0 + 2), chain_general(x4.z - 0.5f, c0 + 2));
    lk.w = sig_diff_clamp(chain_general(x4.w + 0.5f, c0 + 3), chain_general(x4.w - 0.5f, c0 + 3));
    out_l[i] = lk;
}

// ---------------- launch ----------------
extern "C" void kernel_launch(void* const* d_in, const int* in_sizes, int n_in,
                              void* d_out, int out_size)
{
    const float* inputs = (const float*)d_in[0];
    const float* noise  = (const float*)d_in[1];
    const float* m0 = (const float*)d_in[2];
    const float* b0 = (const float*)d_in[3];
    const float* f0 = (const float*)d_in[4];
    const float* m1 = (const float*)d_in[5];
    const float* b1 = (const float*)d_in[6];
    const float* f1 = (const float*)d_in[7];
    const float* m2 = (const float*)d_in[8];
    const float* b2 = (const float*)d_in[9];
    const float* f2 = (const float*)d_in[10];
    const float* m3 = (const float*)d_in[11];
    const float* b3 = (const float*)d_in[12];
    const float* f3 = (const float*)d_in[13];

    float* out = (float*)d_out;
    float* out_outputs;
    float* out_lik;
    int write_outputs;
    if (out_size >= 2 * NC) {
        out_outputs = out;          // (N, C) outputs first
        out_lik     = out + NC;     // then (N, C) likelihood
        write_outputs = 1;
    } else {
        out_outputs = out;
        out_lik     = out;
        write_outputs = 0;
    }

    eb_prelude<<<1, 64>>>(m0, b0, f0, m1, b1, f1, m2, b2, f2, m3, b3, f3);

    int blocks = (NC4 + 255) / 256;
    eb_main_fast<<<blocks, 256>>>((const float4*)inputs, (const float4*)noise,
                                  (float4*)out_outputs, (float4*)out_lik, write_outputs);
    // correctness fallback for nonzero tanh gates; no-ops (uniform early exit)
    // on the fast path.
    eb_main_general<<<blocks, 256>>>((const float4*)inputs, (const float4*)noise,
                                     (float4*)out_lik);
}

// round 5
// speedup vs baseline: 1.7124x; 1.1152x over previous
#include <cuda_runtime.h>
#include <math.h>

#define C_CH 64
#define NPTS 500000
#define NC (NPTS * C_CH)          // 32,000,000
#define NC4 (NC / 4)              // 8,000,000
#define NC8 (NC4 / 2)             // 4,000,000  (ILP-2 split; 4M % 16 == 0)

// ---------------- device-global precomputed parameters ----------------
__device__ float4 g_A4[16];
__device__ float4 g_Bu4[16];
__device__ int    g_fast;

// General path (any f != 0): softplus(m), biases, tanh(f) per channel/layer.
__device__ float g_sp0[C_CH * 3], g_b0v[C_CH * 3], g_tf0[C_CH * 3];
__device__ float g_sp1[C_CH * 9], g_b1v[C_CH * 3], g_tf1[C_CH * 3];
__device__ float g_sp2[C_CH * 9], g_b2v[C_CH * 3], g_tf2[C_CH * 3];
__device__ float g_sp3[C_CH * 3], g_b3v[C_CH],     g_tf3[C_CH];

// ---------------- prelude: parallel softplus phase + per-channel compose ---
__global__ void __launch_bounds__(256)
eb_prelude(
    const float* __restrict__ m0, const float* __restrict__ b0, const float* __restrict__ f0,
    const float* __restrict__ m1, const float* __restrict__ b1, const float* __restrict__ f1,
    const float* __restrict__ m2, const float* __restrict__ b2, const float* __restrict__ f2,
    const float* __restrict__ m3, const float* __restrict__ b3, const float* __restrict__ f3)
{
    __shared__ float s_sp0[C_CH * 3], s_sp1[C_CH * 9], s_sp2[C_CH * 9], s_sp3[C_CH * 3];
    __shared__ float s_b0[C_CH * 3], s_b1[C_CH * 3], s_b2[C_CH * 3], s_b3[C_CH];

    int t = threadIdx.x;          // 256 threads

    // ---- phase 1: all softplus values in parallel (1536 total, 6/thread) ----
    // layout: [0,192) m0 | [192,768) m1 | [768,1344) m2 | [1344,1536) m3
    for (int idx = t; idx < 1536; idx += 256) {
        float m;
        if (idx < 192)        m = m0[idx];
        else if (idx < 768)   m = m1[idx - 192];
        else if (idx < 1344)  m = m2[idx - 768];
        else                  m = m3[idx - 1344];
        float sp = log1pf(expf(m));
        if (idx < 192)        { s_sp0[idx] = sp;        g_sp0[idx] = sp; }
        else if (idx < 768)   { s_sp1[idx - 192] = sp;  g_sp1[idx - 192] = sp; }
        else if (idx < 1344)  { s_sp2[idx - 768] = sp;  g_sp2[idx - 768] = sp; }
        else                  { s_sp3[idx - 1344] = sp; g_sp3[idx - 1344] = sp; }
    }

    // biases -> shared + global
    for (int idx = t; idx < 192; idx += 256) {
        s_b0[idx] = b0[idx]; g_b0v[idx] = s_b0[idx];
        s_b1[idx] = b1[idx]; g_b1v[idx] = s_b1[idx];
        s_b2[idx] = b2[idx]; g_b2v[idx] = s_b2[idx];
    }
    if (t < C_CH) { s_b3[t] = b3[t]; g_b3v[t] = s_b3[t]; }

    // tanh gates + zero check: [0,192) f0 | [192,384) f1 | [384,576) f2 | [576,640) f3
    bool fz = true;
    for (int idx = t; idx < 640; idx += 256) {
        float f;
        if (idx < 192)       f = f0[idx];
        else if (idx < 384)  f = f1[idx - 192];
        else if (idx < 576)  f = f2[idx - 384];
        else                 f = f3[idx - 576];
        if (f != 0.f) fz = false;
        float tf = tanhf(f);
        if (idx < 192)       g_tf0[idx] = tf;
        else if (idx < 384)  g_tf1[idx - 192] = tf;
        else if (idx < 576)  g_tf2[idx - 384] = tf;
        else                 g_tf3[idx - 576] = tf;
    }

    int all_fz = __syncthreads_and(fz ? 1 : 0);
    if (t == 0) g_fast = all_fz;

    // ---- phase 2: compose affine chain per channel (threads 0..63) ----
    if (t < C_CH) {
        int c = t;
        float a0[3], bb[3];
        #pragma unroll
        for (int j = 0; j < 3; j++) { a0[j] = s_sp0[c * 3 + j]; bb[j] = s_b0[c * 3 + j]; }
        float a1[3], bv1[3];
        #pragma unroll
        for (int i = 0; i < 3; i++) {
            float av = 0.f, bv = s_b1[c * 3 + i];
            #pragma unroll
            for (int j = 0; j < 3; j++) {
                av = fmaf(s_sp1[c * 9 + i * 3 + j], a0[j], av);
                bv = fmaf(s_sp1[c * 9 + i * 3 + j], bb[j], bv);
            }
            a1[i] = av; bv1[i] = bv;
        }
        float a2[3], bv2[3];
        #pragma unroll
        for (int i = 0; i < 3; i++) {
            float av = 0.f, bv = s_b2[c * 3 + i];
            #pragma unroll
            for (int j = 0; j < 3; j++) {
                av = fmaf(s_sp2[c * 9 + i * 3 + j], a1[j], av);
                bv = fmaf(s_sp2[c * 9 + i * 3 + j], bv1[j], bv);
            }
            a2[i] = av; bv2[i] = bv;
        }
        float A = 0.f, B = s_b3[c];
        #pragma unroll
        for (int j = 0; j < 3; j++) { A = fmaf(s_sp3[c * 3 + j], a2[j], A); B = fmaf(s_sp3[c * 3 + j], bv2[j], B); }

        ((float*)g_A4)[c]  = A;
        ((float*)g_Bu4)[c] = B + 0.5f * A;
    }
}

// ---------------- likelihood helpers ----------------
__device__ __forceinline__ float sig_diff_clamp(float u, float l)
{
    // sign = -sign(l+u); likelihood = |sigmoid(s*u) - sigmoid(s*l)|, clamped.
    float t = u + l;
    float s = (t > 0.f) ? -1.f : ((t < 0.f) ? 1.f : 0.f);
    float ea = __expf(s * u);
    float eb = __expf(s * l);
    // sig(a)-sig(b) = (e^a - e^b) / ((1+e^a)(1+e^b))
    float d = __fdividef(ea - eb, (1.f + ea) * (1.f + eb));
    return fmaxf(fabsf(d), 1e-9f);
}

// ---------------- fast-path main kernel (affine chain, ILP 2) --------------
__global__ void __launch_bounds__(256)
eb_main_fast(const float4* __restrict__ in, const float4* __restrict__ noise,
             float4* __restrict__ out_o, float4* __restrict__ out_l, int write_outputs)
{
    int i = blockIdx.x * blockDim.x + threadIdx.x;
    if (i >= NC8) return;
    int j = i + NC8;              // NC8 % 16 == 0, so same channel-group as i

    int cg = i & 15;
    float4 A  = g_A4[cg];
    float4 Bu = g_Bu4[cg];

    float4 xa = in[i];
    float4 na = noise[i];
    float4 xb = in[j];
    float4 nb = noise[j];
    xa.x += na.x; xa.y += na.y; xa.z += na.z; xa.w += na.w;
    xb.x += nb.x; xb.y += nb.y; xb.z += nb.z; xb.w += nb.w;
    if (write_outputs) { out_o[i] = xa; out_o[j] = xb; }

    float ua_x = fmaf(A.x, xa.x, Bu.x);
    float ua_y = fmaf(A.y, xa.y, Bu.y);
    float ua_z = fmaf(A.z, xa.z, Bu.z);
    float ua_w = fmaf(A.w, xa.w, Bu.w);
    float ub_x = fmaf(A.x, xb.x, Bu.x);
    float ub_y = fmaf(A.y, xb.y, Bu.y);
    float ub_z = fmaf(A.z, xb.z, Bu.z);
    float ub_w = fmaf(A.w, xb.w, Bu.w);

    float4 la, lb;
    la.x = sig_diff_clamp(ua_x, ua_x - A.x);
    la.y = sig_diff_clamp(ua_y, ua_y - A.y);
    la.z = sig_diff_clamp(ua_z, ua_z - A.z);
    la.w = sig_diff_clamp(ua_w, ua_w - A.w);
    lb.x = sig_diff_clamp(ub_x, ub_x - A.x);
    lb.y = sig_diff_clamp(ub_y, ub_y - A.y);
    lb.z = sig_diff_clamp(ub_z, ub_z - A.z);
    lb.w = sig_diff_clamp(ub_w, ub_w - A.w);

    out_l[i] = la;
    out_l[j] = lb;
}

// ---------------- general-path fallback (small grid, grid-stride) ----------
__device__ float chain_general(float x, int c)
{
    float h[3], h2[3];
    #pragma unroll
    for (int j = 0; j < 3; j++) {
        float v = fmaf(g_sp0[c * 3 + j], x, g_b0v[c * 3 + j]);
        h[j] = v + g_tf0[c * 3 + j] * tanhf(v);
    }
    #pragma unroll
    for (int i = 0; i < 3; i++) {
        float v = g_b1v[c * 3 + i];
        #pragma unroll
        for (int j = 0; j < 3; j++) v = fmaf(g_sp1[c * 9 + i * 3 + j], h[j], v);
        h2[i] = v + g_tf1[c * 3 + i] * tanhf(v);
    }
    #pragma unroll
    for (int i = 0; i < 3; i++) {
        float v = g_b2v[c * 3 + i];
        #pragma unroll
        for (int j = 0; j < 3; j++) v = fmaf(g_sp2[c * 9 + i * 3 + j], h2[j], v);
        h[i] = v + g_tf2[c * 3 + i] * tanhf(v);
    }
    float v = g_b3v[c];
    #pragma unroll
    for (int j = 0; j < 3; j++) v = fmaf(g_sp3[c * 3 + j], h[j], v);
    return v + g_tf3[c] * tanhf(v);
}

__global__ void __launch_bounds__(256)
eb_main_general(const float4* __restrict__ in, const float4* __restrict__ noise,
                float4* __restrict__ out_l)
{
    if (g_fast) return;           // uniform branch: whole (small) grid no-ops

    for (int i = blockIdx.x * blockDim.x + threadIdx.x; i < NC4;
         i += gridDim.x * blockDim.x) {
        int cg = i & 15;
        int c0 = cg * 4;

        float4 x4 = in[i];
        float4 n4 = noise[i];
        x4.x += n4.x; x4.y += n4.y; x4.z += n4.z; x4.w += n4.w;

        float4 lk;
        lk.x = sig_diff_clamp(chain_general(x4.x + 0.5f, c0 + 0), chain_general(x4.x - 0.5f, c0 + 0));
        lk.y = sig_diff_clamp(chain_general(x4.y + 0.5f, c0 + 1), chain_general(x4.y - 0.5f, c0 + 1));
        lk.z = sig_diff_clamp(chain_general(x4.z + 0.5f, c0 + 2), chain_general(x4.z - 0.5f, c0 + 2));
        lk.w = sig_diff_clamp(chain_general(x4.w + 0.5f, c0 + 3), chain_general(x4.w - 0.5f, c0 + 3));
        out_l[i] = lk;
    }
}

// ---------------- launch ----------------
extern "C" void kernel_launch(void* const* d_in, const int* in_sizes, int n_in,
                              void* d_out, int out_size)
{
    const float* inputs = (const float*)d_in[0];
    const float* noise  = (const float*)d_in[1];
    const float* m0 = (const float*)d_in[2];
    const float* b0 = (const float*)d_in[3];
    const float* f0 = (const float*)d_in[4];
    const float* m1 = (const float*)d_in[5];
    const float* b1 = (const float*)d_in[6];
    const float* f1 = (const float*)d_in[7];
    const float* m2 = (const float*)d_in[8];
    const float* b2 = (const float*)d_in[9];
    const float* f2 = (const float*)d_in[10];
    const float* m3 = (const float*)d_in[11];
    const float* b3 = (const float*)d_in[12];
    const float* f3 = (const float*)d_in[13];

    float* out = (float*)d_out;
    float* out_outputs;
    float* out_lik;
    int write_outputs;
    if (out_size >= 2 * NC) {
        out_outputs = out;          // (N, C) outputs first
        out_lik     = out + NC;     // then (N, C) likelihood
        write_outputs = 1;
    } else {
        out_outputs = out;
        out_lik     = out;
        write_outputs = 0;
    }

    eb_prelude<<<1, 256>>>(m0, b0, f0, m1, b1, f1, m2, b2, f2, m3, b3, f3);

    int blocks = (NC8 + 255) / 256;     // 15625
    eb_main_fast<<<blocks, 256>>>((const float4*)inputs, (const float4*)noise,
                                  (float4*)out_outputs, (float4*)out_lik, write_outputs);
    // correctness fallback for nonzero tanh gates; tiny no-op grid on fast path
    eb_main_general<<<1184, 256>>>((const float4*)inputs, (const float4*)noise,
                                   (float4*)out_lik);
}